// round 10
// baseline (speedup 1.0000x reference)
#include <cuda_runtime.h>
#include <cstdint>
#include <math.h>

#define T_   384
#define B_   48
#define H_   256
#define G3   768
#define CSZ  8                 // CTAs per cluster
#define GB   3                 // batches per cluster
#define NCTA 128
#define THR  256               // 8 warps
#define NPASS 6
#define HROW 52                // padded words per k16-row (conflict-free)

// ---------------- scratch ----------------
__device__ float g_gi[(size_t)T_ * B_ * G3];
__device__ float g_ys0[(size_t)T_ * B_ * H_];
__device__ float g_skipc[B_];
__device__ float g_dcar[B_];

// ---------------- helpers ----------------
__device__ __forceinline__ float sigm_fast(float x) {
    return __fdividef(1.f, 1.f + __expf(-x));
}
__device__ __forceinline__ float tanh_fast(float x) {
    return fmaf(2.f, sigm_fast(2.f * x), -1.f);
}

#define FMA4(acc, wv, hv) { acc = fmaf((wv).x,(hv).x,acc); acc = fmaf((wv).y,(hv).y,acc); \
                            acc = fmaf((wv).z,(hv).z,acc); acc = fmaf((wv).w,(hv).w,acc); }

__device__ __forceinline__ void advance_state(float& u, float& d, float& s, float dn) {
    float bup = rintf(u);
    float nu  = (s > 0.f) ? fminf(fmaxf(u + d, 0.f), 1.f) * (1.f - bup) : dn * bup;
    d = (s > 0.f) ? d : dn;
    s = ((ceilf(0.5f / nu) - 1.f) > 0.f) ? 1.f : 0.f;
    u = nu;
}

__device__ __forceinline__ unsigned smem_u32(const void* p) {
    unsigned a;
    asm("{ .reg .u64 t; cvta.to.shared.u64 t, %1; cvt.u32.u64 %0, t; }" : "=r"(a) : "l"(p));
    return a;
}
__device__ __forceinline__ unsigned mapa_u32(unsigned a, unsigned r) {
    unsigned o; asm("mapa.shared::cluster.u32 %0, %1, %2;" : "=r"(o) : "r"(a), "r"(r)); return o;
}
__device__ __forceinline__ void st_clu(unsigned a, float v) {
    asm volatile("st.shared::cluster.f32 [%0], %1;" :: "r"(a), "f"(v) : "memory");
}
__device__ __forceinline__ void st_clu4(unsigned a, float x, float y, float z, float w) {
    asm volatile("st.shared::cluster.v4.f32 [%0], {%1, %2, %3, %4};"
                 :: "r"(a), "f"(x), "f"(y), "f"(z), "f"(w) : "memory");
}
#define CLUSTER_SYNC() do { asm volatile("barrier.cluster.arrive.aligned;" ::: "memory"); \
                            asm volatile("barrier.cluster.wait.aligned;"   ::: "memory"); } while (0)

// ---------------- bulk gi GEMM (unchanged from R4) ----------------
__global__ void __launch_bounds__(128) gemm_xw(const float* __restrict__ x, int layer,
                                               const float* __restrict__ wih) {
    __shared__ float As[16][64];
    __shared__ float Bs[16][64];
    const float* A = layer ? (const float*)g_ys0 : x;
    const float* W = wih + (size_t)layer * G3 * H_;
    const int tid = threadIdx.x;
    const int m0 = blockIdx.x * 64, n0 = blockIdx.y * 64;
    const int tx = tid & 15, ty = tid >> 4;
    float acc[8][4];
#pragma unroll
    for (int i = 0; i < 8; i++)
#pragma unroll
        for (int j = 0; j < 4; j++) acc[i][j] = 0.f;

    for (int kt = 0; kt < 256; kt += 16) {
#pragma unroll
        for (int i = 0; i < 2; i++) {
            int idx = tid + i * 128;
            int row = idx >> 2, k4 = idx & 3;
            float4 a = *(const float4*)&A[(size_t)(m0 + row) * 256 + kt + k4 * 4];
            As[k4*4+0][row] = a.x; As[k4*4+1][row] = a.y;
            As[k4*4+2][row] = a.z; As[k4*4+3][row] = a.w;
            float4 b = *(const float4*)&W[(size_t)(n0 + row) * 256 + kt + k4 * 4];
            Bs[k4*4+0][row] = b.x; Bs[k4*4+1][row] = b.y;
            Bs[k4*4+2][row] = b.z; Bs[k4*4+3][row] = b.w;
        }
        __syncthreads();
#pragma unroll
        for (int kk = 0; kk < 16; kk++) {
            float4 b4 = *(const float4*)&Bs[kk][tx * 4];
            float4 a0 = *(const float4*)&As[kk][ty * 8];
            float4 a1 = *(const float4*)&As[kk][ty * 8 + 4];
            float am[8] = {a0.x, a0.y, a0.z, a0.w, a1.x, a1.y, a1.z, a1.w};
            float bm[4] = {b4.x, b4.y, b4.z, b4.w};
#pragma unroll
            for (int i = 0; i < 8; i++)
#pragma unroll
                for (int j = 0; j < 4; j++)
                    acc[i][j] = fmaf(am[i], bm[j], acc[i][j]);
        }
        __syncthreads();
    }
#pragma unroll
    for (int i = 0; i < 8; i++) {
        float4 o = make_float4(acc[i][0], acc[i][1], acc[i][2], acc[i][3]);
        *(float4*)&g_gi[(size_t)(m0 + ty * 8 + i) * G3 + n0 + tx * 4] = o;
    }
}

// h address helper: unit j (0..255), batch b -> padded smem word index
#define HIDX(j, b) (((j) >> 4) * HROW + (b) * 16 + ((j) & 15))

// ---------------- clustered recurrence (R9 + vectorized exchange) ----------------
__global__ void __launch_bounds__(THR, 1) __cluster_dims__(CSZ, 1, 1)
rec_kernel(int layer,
           const float* __restrict__ hiddens,
           const float* __restrict__ whh,
           const float* __restrict__ bih,
           const float* __restrict__ bhh,
           const float* __restrict__ lw,
           const float* __restrict__ lb,
           float* __restrict__ d_out)
{
    __shared__ __align__(16) float h_p[16 * HROW];   // padded h: row=k16, word=b*16+(j&15)
    __shared__ float gh_s[32][3][GB];
    __shared__ float parts_s[CSZ][GB];
    __shared__ float s_bu[GB], s_sk[GB];

    const int tid  = threadIdx.x;
    const int w    = tid >> 5;
    const int lane = tid & 31;
    unsigned rk; asm("mov.u32 %0, %%cluster_ctarank;" : "=r"(rk));
    const int cid = blockIdx.x / CSZ;
    const int bg0 = cid * GB;

    float* ys      = layer ? d_out : g_ys0;
    float* hs_out  = d_out + (size_t)T_ * B_ * H_ + (size_t)layer * B_ * H_;
    float* tu_out  = d_out + (size_t)T_ * B_ * H_ + 2 * B_ * H_;   // [B][2T]
    const float* gi  = g_gi;
    const float* h0  = hiddens + (size_t)layer * H_;
    const float* wh  = whh + (size_t)layer * G3 * H_;
    const float* bi  = bih + (size_t)layer * G3;
    const float* bh  = bhh + (size_t)layer * G3;
    const float* lwp = lw + (size_t)layer * H_;

    // ---- w_hh slices in registers ----
    const int r2 = lane >> 4, k16 = lane & 15;
    float4 wv[NPASS][4];
    const float4* whp = (const float4*)wh;
#pragma unroll
    for (int p = 0; p < NPASS; p++) {
        int row = (p >> 1) * 256 + (int)rk * 32 + w * 4 + (p & 1) * 2 + r2;
#pragma unroll
        for (int i = 0; i < 4; i++) wv[p][i] = whp[(size_t)row * 64 + k16 * 4 + i];
    }
    // epilogue constants (warps 0-2: lane -> (batch=w, unit=lane))
    const int eb = w, eu = lane, egu = (int)rk * 32 + eu;
    float bir = 0, biz = 0, bin = 0, bhr = 0, bhz = 0, bhn = 0, lwj = 0;
    if (w < 3) {
        bir = bi[egu]; biz = bi[256 + egu]; bin = bi[512 + egu];
        bhr = bh[egu]; bhz = bh[256 + egu]; bhn = bh[512 + egu];
        lwj = lwp[egu];
    }
    // skip-state (warp 3, lanes<GB; redundant per CTA, deterministic)
    float su = 1.f, sd = 0.f, ss = 0.f, lb_ = 0.f;
    if (w == 3 && lane < GB) {
        lb_ = lb[layer];
        if (layer) { sd = g_dcar[bg0 + lane]; ss = g_skipc[bg0 + lane]; }
    }
    // DSMEM peer addresses
    unsigned hb = smem_u32(h_p), pb = smem_u32(parts_s);
    unsigned peer_h[CSZ], peer_p[CSZ];
#pragma unroll
    for (int r = 0; r < CSZ; r++) { peer_h[r] = mapa_u32(hb, r); peer_p[r] = mapa_u32(pb, r); }

    // init h (each CTA holds full h for its 3 batches, padded layout)
    for (int i = tid; i < GB * H_; i += THR) {
        int b = i >> 8, j = i & 255;
        h_p[HIDX(j, b)] = h0[j];
    }
    __syncthreads();
    CLUSTER_SYNC();

    for (int t = 0; t < T_; t++) {
        // gi prefetch for this step's epilogue (hidden under GEMV)
        float gir = 0.f, giz = 0.f, gin = 0.f;
        if (w < 3) {
            const float* gp = gi + ((size_t)t * B_ + bg0 + eb) * G3 + egu;
            gir = gp[0]; giz = gp[256]; gin = gp[512];
        }
        // skip-state update from step t-1 partials
        if (w == 3 && lane < GB) {
            if (t > 0) {
                float ps = 0.f;
#pragma unroll
                for (int r = 0; r < CSZ; r++) ps += parts_s[r][lane];
                advance_state(su, sd, ss, sigm_fast(ps + lb_));
            }
            float bu = rintf(su);
            s_bu[lane] = bu; s_sk[lane] = ss;
            if (rk == 0) tu_out[(size_t)(bg0 + lane) * (2 * T_) + layer * T_ + t] = bu;
        }
        // load this lane's h k-slice (conflict-free padded rows)
        float4 hreg[GB][4];
#pragma unroll
        for (int b = 0; b < GB; b++)
#pragma unroll
            for (int i = 0; i < 4; i++)
                hreg[b][i] = *(const float4*)&h_p[k16 * HROW + b * 16 + i * 4];
        // GEMV: NPASS passes, each = 1 gate-row per lane-half x 3 batches
#pragma unroll
        for (int p = 0; p < NPASS; p++) {
            float a0 = 0.f, a1 = 0.f, a2 = 0.f;
#pragma unroll
            for (int i = 0; i < 4; i++) {
                FMA4(a0, wv[p][i], hreg[0][i]);
                FMA4(a1, wv[p][i], hreg[1][i]);
                FMA4(a2, wv[p][i], hreg[2][i]);
            }
#pragma unroll
            for (int m = 8; m >= 1; m >>= 1) {
                a0 += __shfl_xor_sync(0xffffffffu, a0, m);
                a1 += __shfl_xor_sync(0xffffffffu, a1, m);
                a2 += __shfl_xor_sync(0xffffffffu, a2, m);
            }
            if (k16 == 0) {
                int u = w * 4 + (p & 1) * 2 + r2, g = p >> 1;
                gh_s[u][g][0] = a0; gh_s[u][g][1] = a1; gh_s[u][g][2] = a2;
            }
        }
        __syncthreads();   // gh_s, s_bu, s_sk ready

        if (w < 3) {
            float ghr = gh_s[eu][0][eb], ghz = gh_s[eu][1][eb], ghn = gh_s[eu][2][eb];
            float bu = s_bu[eb], sk = s_sk[eb];
            float hprev = h_p[HIDX(egu, eb)];
            float r = sigm_fast(gir + bir + ghr + bhr);
            float z = sigm_fast(giz + biz + ghz + bhz);
            float n = tanh_fast(gin + bin + r * (ghn + bhn));
            float cand = (1.f - z) * n + z * hprev;
            float hns = cand * bu;
            float nh = (sk > 0.f) ? hprev * (1.f - bu) : hns;

            // ---- vectorized exchange: gather 4 consecutive units into lane%4==0 ----
            float v1 = __shfl_down_sync(0xffffffffu, nh, 1);
            float v2 = __shfl_down_sync(0xffffffffu, nh, 2);
            float v3 = __shfl_down_sync(0xffffffffu, nh, 3);
            if ((lane & 3) == 0) {
                unsigned off = (unsigned)HIDX(egu, eb) * 4u;   // 16B-aligned
#pragma unroll
                for (int r7 = 0; r7 < CSZ; r7++)
                    st_clu4(peer_h[r7] + off, nh, v1, v2, v3); // includes self
                float4 o = make_float4(nh, v1, v2, v3);
                *(float4*)&ys[((size_t)t * B_ + bg0 + eb) * H_ + egu] = o;
                if (t == T_ - 1) *(float4*)&hs_out[(size_t)(bg0 + eb) * H_ + egu] = o;
            }
            float pd = hns * lwj;
#pragma unroll
            for (int m = 16; m >= 1; m >>= 1) pd += __shfl_xor_sync(0xffffffffu, pd, m);
            if (lane == 0) {
                unsigned poff = (unsigned)((int)rk * GB + eb) * 4u;
#pragma unroll
                for (int r7 = 0; r7 < CSZ; r7++)
                    st_clu(peer_p[r7] + poff, pd);             // includes self
            }
        }
        CLUSTER_SYNC();    // publish h slices + partials cluster-wide
    }

    // layer-0 final carry (skip, d) for layer 1
    if (layer == 0 && w == 3 && lane < GB && rk == 0) {
        float ps = 0.f;
#pragma unroll
        for (int r = 0; r < CSZ; r++) ps += parts_s[r][lane];
        advance_state(su, sd, ss, sigm_fast(ps + lb_));
        g_dcar[bg0 + lane] = sd; g_skipc[bg0 + lane] = ss;
    }
}

// ---------------- launcher ----------------
extern "C" void kernel_launch(void* const* d_in, const int* in_sizes, int n_in,
                              void* d_out, int out_size) {
    const float* x   = (const float*)d_in[0];
    const float* hid = (const float*)d_in[1];
    const float* wih = (const float*)d_in[2];
    const float* whh = (const float*)d_in[3];
    const float* bih = (const float*)d_in[4];
    const float* bhh = (const float*)d_in[5];
    const float* lw  = (const float*)d_in[6];
    const float* lb  = (const float*)d_in[7];
    float* out = (float*)d_out;

    dim3 ggrid(T_ * B_ / 64, G3 / 64);   // (288, 12)
    gemm_xw<<<ggrid, 128>>>(x, 0, wih);
    rec_kernel<<<NCTA, THR>>>(0, hid, whh, bih, bhh, lw, lb, out);
    gemm_xw<<<ggrid, 128>>>(x, 1, wih);
    rec_kernel<<<NCTA, THR>>>(1, hid, whh, bih, bhh, lw, lb, out);
}

// round 11
// speedup vs baseline: 1.0946x; 1.0946x over previous
#include <cuda_runtime.h>
#include <cstdint>
#include <math.h>

#define T_   384
#define B_   48
#define H_   256
#define G3   768
#define CSZ  8                 // CTAs per cluster
#define GB   3                 // batches per cluster
#define NCTA 128
#define THR  256               // 8 warps
#define NPASS 6
#define HROW 52                // padded words per k16-row (conflict-free)

// ---------------- scratch ----------------
__device__ float g_gi[(size_t)T_ * B_ * G3];
__device__ float g_ys0[(size_t)T_ * B_ * H_];
__device__ float g_skipc[B_];
__device__ float g_dcar[B_];

// ---------------- helpers ----------------
__device__ __forceinline__ float sigm_fast(float x) {
    return __fdividef(1.f, 1.f + __expf(-x));
}
__device__ __forceinline__ float tanh_fast(float x) {
    return fmaf(2.f, sigm_fast(2.f * x), -1.f);
}

#define FMA4(acc, wv, hv) { acc = fmaf((wv).x,(hv).x,acc); acc = fmaf((wv).y,(hv).y,acc); \
                            acc = fmaf((wv).z,(hv).z,acc); acc = fmaf((wv).w,(hv).w,acc); }

__device__ __forceinline__ void advance_state(float& u, float& d, float& s, float dn) {
    float bup = rintf(u);
    float nu  = (s > 0.f) ? fminf(fmaxf(u + d, 0.f), 1.f) * (1.f - bup) : dn * bup;
    d = (s > 0.f) ? d : dn;
    s = ((ceilf(0.5f / nu) - 1.f) > 0.f) ? 1.f : 0.f;
    u = nu;
}

__device__ __forceinline__ unsigned smem_u32(const void* p) {
    unsigned a;
    asm("{ .reg .u64 t; cvta.to.shared.u64 t, %1; cvt.u32.u64 %0, t; }" : "=r"(a) : "l"(p));
    return a;
}
__device__ __forceinline__ unsigned mapa_u32(unsigned a, unsigned r) {
    unsigned o; asm("mapa.shared::cluster.u32 %0, %1, %2;" : "=r"(o) : "r"(a), "r"(r)); return o;
}
__device__ __forceinline__ void st_clu(unsigned a, float v) {
    asm volatile("st.shared::cluster.f32 [%0], %1;" :: "r"(a), "f"(v) : "memory");
}
#define CLUSTER_ARRIVE() asm volatile("barrier.cluster.arrive.aligned;" ::: "memory")
#define CLUSTER_WAIT()   asm volatile("barrier.cluster.wait.aligned;"   ::: "memory")
#define CLUSTER_SYNC() do { CLUSTER_ARRIVE(); CLUSTER_WAIT(); } while (0)

// ---------------- bulk gi GEMM (unchanged) ----------------
__global__ void __launch_bounds__(128) gemm_xw(const float* __restrict__ x, int layer,
                                               const float* __restrict__ wih) {
    __shared__ float As[16][64];
    __shared__ float Bs[16][64];
    const float* A = layer ? (const float*)g_ys0 : x;
    const float* W = wih + (size_t)layer * G3 * H_;
    const int tid = threadIdx.x;
    const int m0 = blockIdx.x * 64, n0 = blockIdx.y * 64;
    const int tx = tid & 15, ty = tid >> 4;
    float acc[8][4];
#pragma unroll
    for (int i = 0; i < 8; i++)
#pragma unroll
        for (int j = 0; j < 4; j++) acc[i][j] = 0.f;

    for (int kt = 0; kt < 256; kt += 16) {
#pragma unroll
        for (int i = 0; i < 2; i++) {
            int idx = tid + i * 128;
            int row = idx >> 2, k4 = idx & 3;
            float4 a = *(const float4*)&A[(size_t)(m0 + row) * 256 + kt + k4 * 4];
            As[k4*4+0][row] = a.x; As[k4*4+1][row] = a.y;
            As[k4*4+2][row] = a.z; As[k4*4+3][row] = a.w;
            float4 b = *(const float4*)&W[(size_t)(n0 + row) * 256 + kt + k4 * 4];
            Bs[k4*4+0][row] = b.x; Bs[k4*4+1][row] = b.y;
            Bs[k4*4+2][row] = b.z; Bs[k4*4+3][row] = b.w;
        }
        __syncthreads();
#pragma unroll
        for (int kk = 0; kk < 16; kk++) {
            float4 b4 = *(const float4*)&Bs[kk][tx * 4];
            float4 a0 = *(const float4*)&As[kk][ty * 8];
            float4 a1 = *(const float4*)&As[kk][ty * 8 + 4];
            float am[8] = {a0.x, a0.y, a0.z, a0.w, a1.x, a1.y, a1.z, a1.w};
            float bm[4] = {b4.x, b4.y, b4.z, b4.w};
#pragma unroll
            for (int i = 0; i < 8; i++)
#pragma unroll
                for (int j = 0; j < 4; j++)
                    acc[i][j] = fmaf(am[i], bm[j], acc[i][j]);
        }
        __syncthreads();
    }
#pragma unroll
    for (int i = 0; i < 8; i++) {
        float4 o = make_float4(acc[i][0], acc[i][1], acc[i][2], acc[i][3]);
        *(float4*)&g_gi[(size_t)(m0 + ty * 8 + i) * G3 + n0 + tx * 4] = o;
    }
}

// h address helper: unit j (0..255), batch b -> padded smem word index
#define HIDX(j, b) (((j) >> 4) * HROW + (b) * 16 + ((j) & 15))

// ---------------- clustered recurrence (R9 + split cluster barrier) ----------------
__global__ void __launch_bounds__(THR, 1) __cluster_dims__(CSZ, 1, 1)
rec_kernel(int layer,
           const float* __restrict__ hiddens,
           const float* __restrict__ whh,
           const float* __restrict__ bih,
           const float* __restrict__ bhh,
           const float* __restrict__ lw,
           const float* __restrict__ lb,
           float* __restrict__ d_out)
{
    __shared__ __align__(16) float h_p[16 * HROW];   // padded h: row=k16, word=b*16+(j&15)
    __shared__ float gh_s[32][3][GB];
    __shared__ float parts_s[CSZ][GB];
    __shared__ float s_bu[GB], s_sk[GB];

    const int tid  = threadIdx.x;
    const int w    = tid >> 5;
    const int lane = tid & 31;
    unsigned rk; asm("mov.u32 %0, %%cluster_ctarank;" : "=r"(rk));
    const int cid = blockIdx.x / CSZ;
    const int bg0 = cid * GB;

    float* ys      = layer ? d_out : g_ys0;
    float* hs_out  = d_out + (size_t)T_ * B_ * H_ + (size_t)layer * B_ * H_;
    float* tu_out  = d_out + (size_t)T_ * B_ * H_ + 2 * B_ * H_;   // [B][2T]
    const float* gi  = g_gi;
    const float* h0  = hiddens + (size_t)layer * H_;
    const float* wh  = whh + (size_t)layer * G3 * H_;
    const float* bi  = bih + (size_t)layer * G3;
    const float* bh  = bhh + (size_t)layer * G3;
    const float* lwp = lw + (size_t)layer * H_;

    // ---- w_hh slices in registers ----
    const int r2 = lane >> 4, k16 = lane & 15;
    float4 wv[NPASS][4];
    const float4* whp = (const float4*)wh;
#pragma unroll
    for (int p = 0; p < NPASS; p++) {
        int row = (p >> 1) * 256 + (int)rk * 32 + w * 4 + (p & 1) * 2 + r2;
#pragma unroll
        for (int i = 0; i < 4; i++) wv[p][i] = whp[(size_t)row * 64 + k16 * 4 + i];
    }
    // epilogue constants (warps 0-2: lane -> (batch=w, unit=lane))
    const int eb = w, eu = lane, egu = (int)rk * 32 + eu;
    float bir = 0, biz = 0, bin = 0, bhr = 0, bhz = 0, bhn = 0, lwj = 0;
    if (w < 3) {
        bir = bi[egu]; biz = bi[256 + egu]; bin = bi[512 + egu];
        bhr = bh[egu]; bhz = bh[256 + egu]; bhn = bh[512 + egu];
        lwj = lwp[egu];
    }
    // skip-state (warp 3, lanes<GB; redundant per CTA, deterministic)
    float su = 1.f, sd = 0.f, ss = 0.f, lb_ = 0.f;
    if (w == 3 && lane < GB) {
        lb_ = lb[layer];
        if (layer) { sd = g_dcar[bg0 + lane]; ss = g_skipc[bg0 + lane]; }
    }
    // DSMEM peer addresses
    unsigned hb = smem_u32(h_p), pb = smem_u32(parts_s);
    unsigned peer_h[CSZ], peer_p[CSZ];
#pragma unroll
    for (int r = 0; r < CSZ; r++) { peer_h[r] = mapa_u32(hb, r); peer_p[r] = mapa_u32(pb, r); }

    // init h (each CTA holds full h for its 3 batches, padded layout)
    for (int i = tid; i < GB * H_; i += THR) {
        int b = i >> 8, j = i & 255;
        h_p[HIDX(j, b)] = h0[j];
    }
    __syncthreads();
    CLUSTER_SYNC();

    // gi prefetch for t=0
    float gir = 0.f, giz = 0.f, gin = 0.f;
    if (w < 3) {
        const float* gp = gi + ((size_t)bg0 + eb) * G3 + egu;
        gir = gp[0]; giz = gp[256]; gin = gp[512];
    }

    for (int t = 0; t < T_; t++) {
        // skip-state update from step t-1 partials
        if (w == 3 && lane < GB) {
            if (t > 0) {
                float ps = 0.f;
#pragma unroll
                for (int r = 0; r < CSZ; r++) ps += parts_s[r][lane];
                advance_state(su, sd, ss, sigm_fast(ps + lb_));
            }
            float bu = rintf(su);
            s_bu[lane] = bu; s_sk[lane] = ss;
            if (rk == 0) tu_out[(size_t)(bg0 + lane) * (2 * T_) + layer * T_ + t] = bu;
        }
        // load this lane's h k-slice (conflict-free padded rows)
        float4 hreg[GB][4];
#pragma unroll
        for (int b = 0; b < GB; b++)
#pragma unroll
            for (int i = 0; i < 4; i++)
                hreg[b][i] = *(const float4*)&h_p[k16 * HROW + b * 16 + i * 4];
        // GEMV: NPASS passes, each = 1 gate-row per lane-half x 3 batches
#pragma unroll
        for (int p = 0; p < NPASS; p++) {
            float a0 = 0.f, a1 = 0.f, a2 = 0.f;
#pragma unroll
            for (int i = 0; i < 4; i++) {
                FMA4(a0, wv[p][i], hreg[0][i]);
                FMA4(a1, wv[p][i], hreg[1][i]);
                FMA4(a2, wv[p][i], hreg[2][i]);
            }
#pragma unroll
            for (int m = 8; m >= 1; m >>= 1) {
                a0 += __shfl_xor_sync(0xffffffffu, a0, m);
                a1 += __shfl_xor_sync(0xffffffffu, a1, m);
                a2 += __shfl_xor_sync(0xffffffffu, a2, m);
            }
            if (k16 == 0) {
                int u = w * 4 + (p & 1) * 2 + r2, g = p >> 1;
                gh_s[u][g][0] = a0; gh_s[u][g][1] = a1; gh_s[u][g][2] = a2;
            }
        }
        __syncthreads();   // gh_s, s_bu, s_sk ready

        float nh = 0.f;
        if (w < 3) {
            float ghr = gh_s[eu][0][eb], ghz = gh_s[eu][1][eb], ghn = gh_s[eu][2][eb];
            float bu = s_bu[eb], sk = s_sk[eb];
            float hprev = h_p[HIDX(egu, eb)];
            float r = sigm_fast(gir + bir + ghr + bhr);
            float z = sigm_fast(giz + biz + ghz + bhz);
            float n = tanh_fast(gin + bin + r * (ghn + bhn));
            float cand = (1.f - z) * n + z * hprev;
            float hns = cand * bu;
            nh = (sk > 0.f) ? hprev * (1.f - bu) : hns;
            h_p[HIDX(egu, eb)] = nh;
            unsigned off = (unsigned)HIDX(egu, eb) * 4u;
#pragma unroll
            for (int r7 = 0; r7 < CSZ; r7++)
                if (r7 != (int)rk) st_clu(peer_h[r7] + off, nh);
            float pd = hns * lwj;
#pragma unroll
            for (int m = 16; m >= 1; m >>= 1) pd += __shfl_xor_sync(0xffffffffu, pd, m);
            if (lane == 0) {
                parts_s[rk][eb] = pd;
                unsigned poff = (unsigned)((int)rk * GB + eb) * 4u;
#pragma unroll
                for (int r7 = 0; r7 < CSZ; r7++)
                    if (r7 != (int)rk) st_clu(peer_p[r7] + poff, pd);
            }
        }

        // ---- split barrier: publish DSMEM stores now, overlap the rest ----
        CLUSTER_ARRIVE();

        if (w < 3) {
            ys[((size_t)t * B_ + bg0 + eb) * H_ + egu] = nh;
            if (t == T_ - 1) hs_out[(size_t)(bg0 + eb) * H_ + egu] = nh;
            if (t + 1 < T_) {                 // gi prefetch for t+1 flies during the wait
                const float* gp = gi + ((size_t)(t + 1) * B_ + bg0 + eb) * G3 + egu;
                gir = gp[0]; giz = gp[256]; gin = gp[512];
            }
        }

        CLUSTER_WAIT();
    }

    // layer-0 final carry (skip, d) for layer 1
    if (layer == 0 && w == 3 && lane < GB && rk == 0) {
        float ps = 0.f;
#pragma unroll
        for (int r = 0; r < CSZ; r++) ps += parts_s[r][lane];
        advance_state(su, sd, ss, sigm_fast(ps + lb_));
        g_dcar[bg0 + lane] = sd; g_skipc[bg0 + lane] = ss;
    }
}

// ---------------- launcher ----------------
extern "C" void kernel_launch(void* const* d_in, const int* in_sizes, int n_in,
                              void* d_out, int out_size) {
    const float* x   = (const float*)d_in[0];
    const float* hid = (const float*)d_in[1];
    const float* wih = (const float*)d_in[2];
    const float* whh = (const float*)d_in[3];
    const float* bih = (const float*)d_in[4];
    const float* bhh = (const float*)d_in[5];
    const float* lw  = (const float*)d_in[6];
    const float* lb  = (const float*)d_in[7];
    float* out = (float*)d_out;

    dim3 ggrid(T_ * B_ / 64, G3 / 64);   // (288, 12)
    gemm_xw<<<ggrid, 128>>>(x, 0, wih);
    rec_kernel<<<NCTA, THR>>>(0, hid, whh, bih, bhh, lw, lb, out);
    gemm_xw<<<ggrid, 128>>>(x, 1, wih);
    rec_kernel<<<NCTA, THR>>>(1, hid, whh, bih, bhh, lw, lb, out);
}

// round 12
// speedup vs baseline: 1.1069x; 1.0112x over previous
#include <cuda_runtime.h>
#include <cstdint>
#include <math.h>

#define T_   384
#define B_   48
#define H_   256
#define G3   768
#define CSZ  8                 // CTAs per cluster
#define GB   3                 // batches per cluster
#define NCTA 128
#define THR  256               // 8 warps
#define NPASS 6
#define HROW 52                // padded words per k16-row (conflict-free)
#define GROW 132               // GEMM smem row pad (words); 132*4B rows, 16B-aligned

// ---------------- scratch ----------------
__device__ float g_gi[(size_t)T_ * B_ * G3];
__device__ float g_ys0[(size_t)T_ * B_ * H_];
__device__ float g_skipc[B_];
__device__ float g_dcar[B_];

// ---------------- helpers ----------------
__device__ __forceinline__ float sigm_fast(float x) {
    return __fdividef(1.f, 1.f + __expf(-x));
}
__device__ __forceinline__ float tanh_fast(float x) {
    return fmaf(2.f, sigm_fast(2.f * x), -1.f);
}

#define FMA4(acc, wv, hv) { acc = fmaf((wv).x,(hv).x,acc); acc = fmaf((wv).y,(hv).y,acc); \
                            acc = fmaf((wv).z,(hv).z,acc); acc = fmaf((wv).w,(hv).w,acc); }

__device__ __forceinline__ void advance_state(float& u, float& d, float& s, float dn) {
    float bup = rintf(u);
    float nu  = (s > 0.f) ? fminf(fmaxf(u + d, 0.f), 1.f) * (1.f - bup) : dn * bup;
    d = (s > 0.f) ? d : dn;
    s = ((ceilf(0.5f / nu) - 1.f) > 0.f) ? 1.f : 0.f;
    u = nu;
}

__device__ __forceinline__ unsigned smem_u32(const void* p) {
    unsigned a;
    asm("{ .reg .u64 t; cvta.to.shared.u64 t, %1; cvt.u32.u64 %0, t; }" : "=r"(a) : "l"(p));
    return a;
}
__device__ __forceinline__ unsigned mapa_u32(unsigned a, unsigned r) {
    unsigned o; asm("mapa.shared::cluster.u32 %0, %1, %2;" : "=r"(o) : "r"(a), "r"(r)); return o;
}
__device__ __forceinline__ void st_clu(unsigned a, float v) {
    asm volatile("st.shared::cluster.f32 [%0], %1;" :: "r"(a), "f"(v) : "memory");
}
#define CLUSTER_ARRIVE() asm volatile("barrier.cluster.arrive.aligned;" ::: "memory")
#define CLUSTER_WAIT()   asm volatile("barrier.cluster.wait.aligned;"   ::: "memory")
#define CLUSTER_SYNC() do { CLUSTER_ARRIVE(); CLUSTER_WAIT(); } while (0)

// ---------------- bulk gi GEMM: 128x128 tile, 8x8/thread, 1.0 B/FMA ----------------
// C[m][n] = sum_k A[m][k] * W[n][k]; A: [18432][256], W: [768][256]
__global__ void __launch_bounds__(256) gemm_xw(const float* __restrict__ x, int layer,
                                               const float* __restrict__ wih) {
    __shared__ float As[16][GROW];
    __shared__ float Bs[16][GROW];
    const float* A = layer ? (const float*)g_ys0 : x;
    const float* W = wih + (size_t)layer * G3 * H_;
    const int tid = threadIdx.x;
    const int m0 = blockIdx.x * 128, n0 = blockIdx.y * 128;
    const int tx = tid & 15, ty = tid >> 4;   // 16x16 thread grid
    float acc[8][8];
#pragma unroll
    for (int i = 0; i < 8; i++)
#pragma unroll
        for (int j = 0; j < 8; j++) acc[i][j] = 0.f;

    for (int kt = 0; kt < 256; kt += 16) {
        // stage 128 rows x 16 k for A and B: 512 float4 each, 2 per thread
#pragma unroll
        for (int i = 0; i < 2; i++) {
            int idx = tid + i * 256;          // 0..511
            int row = idx >> 2, k4 = idx & 3;
            float4 a = *(const float4*)&A[(size_t)(m0 + row) * 256 + kt + k4 * 4];
            As[k4*4+0][row] = a.x; As[k4*4+1][row] = a.y;
            As[k4*4+2][row] = a.z; As[k4*4+3][row] = a.w;
            float4 b = *(const float4*)&W[(size_t)(n0 + row) * 256 + kt + k4 * 4];
            Bs[k4*4+0][row] = b.x; Bs[k4*4+1][row] = b.y;
            Bs[k4*4+2][row] = b.z; Bs[k4*4+3][row] = b.w;
        }
        __syncthreads();
#pragma unroll
        for (int kk = 0; kk < 16; kk++) {
            float4 a0 = *(const float4*)&As[kk][ty * 8];
            float4 a1 = *(const float4*)&As[kk][ty * 8 + 4];
            float4 b0 = *(const float4*)&Bs[kk][tx * 8];
            float4 b1 = *(const float4*)&Bs[kk][tx * 8 + 4];
            float am[8] = {a0.x, a0.y, a0.z, a0.w, a1.x, a1.y, a1.z, a1.w};
            float bm[8] = {b0.x, b0.y, b0.z, b0.w, b1.x, b1.y, b1.z, b1.w};
#pragma unroll
            for (int i = 0; i < 8; i++)
#pragma unroll
                for (int j = 0; j < 8; j++)
                    acc[i][j] = fmaf(am[i], bm[j], acc[i][j]);
        }
        __syncthreads();
    }
#pragma unroll
    for (int i = 0; i < 8; i++) {
        size_t ro = (size_t)(m0 + ty * 8 + i) * G3 + n0 + tx * 8;
        *(float4*)&g_gi[ro]     = make_float4(acc[i][0], acc[i][1], acc[i][2], acc[i][3]);
        *(float4*)&g_gi[ro + 4] = make_float4(acc[i][4], acc[i][5], acc[i][6], acc[i][7]);
    }
}

// h address helper: unit j (0..255), batch b -> padded smem word index
#define HIDX(j, b) (((j) >> 4) * HROW + (b) * 16 + ((j) & 15))

// ---------------- clustered recurrence (identical to R11) ----------------
__global__ void __launch_bounds__(THR, 1) __cluster_dims__(CSZ, 1, 1)
rec_kernel(int layer,
           const float* __restrict__ hiddens,
           const float* __restrict__ whh,
           const float* __restrict__ bih,
           const float* __restrict__ bhh,
           const float* __restrict__ lw,
           const float* __restrict__ lb,
           float* __restrict__ d_out)
{
    __shared__ __align__(16) float h_p[16 * HROW];   // padded h: row=k16, word=b*16+(j&15)
    __shared__ float gh_s[32][3][GB];
    __shared__ float parts_s[CSZ][GB];
    __shared__ float s_bu[GB], s_sk[GB];

    const int tid  = threadIdx.x;
    const int w    = tid >> 5;
    const int lane = tid & 31;
    unsigned rk; asm("mov.u32 %0, %%cluster_ctarank;" : "=r"(rk));
    const int cid = blockIdx.x / CSZ;
    const int bg0 = cid * GB;

    float* ys      = layer ? d_out : g_ys0;
    float* hs_out  = d_out + (size_t)T_ * B_ * H_ + (size_t)layer * B_ * H_;
    float* tu_out  = d_out + (size_t)T_ * B_ * H_ + 2 * B_ * H_;   // [B][2T]
    const float* gi  = g_gi;
    const float* h0  = hiddens + (size_t)layer * H_;
    const float* wh  = whh + (size_t)layer * G3 * H_;
    const float* bi  = bih + (size_t)layer * G3;
    const float* bh  = bhh + (size_t)layer * G3;
    const float* lwp = lw + (size_t)layer * H_;

    // ---- w_hh slices in registers ----
    const int r2 = lane >> 4, k16 = lane & 15;
    float4 wv[NPASS][4];
    const float4* whp = (const float4*)wh;
#pragma unroll
    for (int p = 0; p < NPASS; p++) {
        int row = (p >> 1) * 256 + (int)rk * 32 + w * 4 + (p & 1) * 2 + r2;
#pragma unroll
        for (int i = 0; i < 4; i++) wv[p][i] = whp[(size_t)row * 64 + k16 * 4 + i];
    }
    // epilogue constants (warps 0-2: lane -> (batch=w, unit=lane))
    const int eb = w, eu = lane, egu = (int)rk * 32 + eu;
    float bir = 0, biz = 0, bin = 0, bhr = 0, bhz = 0, bhn = 0, lwj = 0;
    if (w < 3) {
        bir = bi[egu]; biz = bi[256 + egu]; bin = bi[512 + egu];
        bhr = bh[egu]; bhz = bh[256 + egu]; bhn = bh[512 + egu];
        lwj = lwp[egu];
    }
    // skip-state (warp 3, lanes<GB; redundant per CTA, deterministic)
    float su = 1.f, sd = 0.f, ss = 0.f, lb_ = 0.f;
    if (w == 3 && lane < GB) {
        lb_ = lb[layer];
        if (layer) { sd = g_dcar[bg0 + lane]; ss = g_skipc[bg0 + lane]; }
    }
    // DSMEM peer addresses
    unsigned hb = smem_u32(h_p), pb = smem_u32(parts_s);
    unsigned peer_h[CSZ], peer_p[CSZ];
#pragma unroll
    for (int r = 0; r < CSZ; r++) { peer_h[r] = mapa_u32(hb, r); peer_p[r] = mapa_u32(pb, r); }

    // init h (each CTA holds full h for its 3 batches, padded layout)
    for (int i = tid; i < GB * H_; i += THR) {
        int b = i >> 8, j = i & 255;
        h_p[HIDX(j, b)] = h0[j];
    }
    __syncthreads();
    CLUSTER_SYNC();

    // gi prefetch for t=0
    float gir = 0.f, giz = 0.f, gin = 0.f;
    if (w < 3) {
        const float* gp = gi + ((size_t)bg0 + eb) * G3 + egu;
        gir = gp[0]; giz = gp[256]; gin = gp[512];
    }

    for (int t = 0; t < T_; t++) {
        // skip-state update from step t-1 partials
        if (w == 3 && lane < GB) {
            if (t > 0) {
                float ps = 0.f;
#pragma unroll
                for (int r = 0; r < CSZ; r++) ps += parts_s[r][lane];
                advance_state(su, sd, ss, sigm_fast(ps + lb_));
            }
            float bu = rintf(su);
            s_bu[lane] = bu; s_sk[lane] = ss;
            if (rk == 0) tu_out[(size_t)(bg0 + lane) * (2 * T_) + layer * T_ + t] = bu;
        }
        // load this lane's h k-slice (conflict-free padded rows)
        float4 hreg[GB][4];
#pragma unroll
        for (int b = 0; b < GB; b++)
#pragma unroll
            for (int i = 0; i < 4; i++)
                hreg[b][i] = *(const float4*)&h_p[k16 * HROW + b * 16 + i * 4];
        // GEMV: NPASS passes, each = 1 gate-row per lane-half x 3 batches
#pragma unroll
        for (int p = 0; p < NPASS; p++) {
            float a0 = 0.f, a1 = 0.f, a2 = 0.f;
#pragma unroll
            for (int i = 0; i < 4; i++) {
                FMA4(a0, wv[p][i], hreg[0][i]);
                FMA4(a1, wv[p][i], hreg[1][i]);
                FMA4(a2, wv[p][i], hreg[2][i]);
            }
#pragma unroll
            for (int m = 8; m >= 1; m >>= 1) {
                a0 += __shfl_xor_sync(0xffffffffu, a0, m);
                a1 += __shfl_xor_sync(0xffffffffu, a1, m);
                a2 += __shfl_xor_sync(0xffffffffu, a2, m);
            }
            if (k16 == 0) {
                int u = w * 4 + (p & 1) * 2 + r2, g = p >> 1;
                gh_s[u][g][0] = a0; gh_s[u][g][1] = a1; gh_s[u][g][2] = a2;
            }
        }
        __syncthreads();   // gh_s, s_bu, s_sk ready

        float nh = 0.f;
        if (w < 3) {
            float ghr = gh_s[eu][0][eb], ghz = gh_s[eu][1][eb], ghn = gh_s[eu][2][eb];
            float bu = s_bu[eb], sk = s_sk[eb];
            float hprev = h_p[HIDX(egu, eb)];
            float r = sigm_fast(gir + bir + ghr + bhr);
            float z = sigm_fast(giz + biz + ghz + bhz);
            float n = tanh_fast(gin + bin + r * (ghn + bhn));
            float cand = (1.f - z) * n + z * hprev;
            float hns = cand * bu;
            nh = (sk > 0.f) ? hprev * (1.f - bu) : hns;
            h_p[HIDX(egu, eb)] = nh;
            unsigned off = (unsigned)HIDX(egu, eb) * 4u;
#pragma unroll
            for (int r7 = 0; r7 < CSZ; r7++)
                if (r7 != (int)rk) st_clu(peer_h[r7] + off, nh);
            float pd = hns * lwj;
#pragma unroll
            for (int m = 16; m >= 1; m >>= 1) pd += __shfl_xor_sync(0xffffffffu, pd, m);
            if (lane == 0) {
                parts_s[rk][eb] = pd;
                unsigned poff = (unsigned)((int)rk * GB + eb) * 4u;
#pragma unroll
                for (int r7 = 0; r7 < CSZ; r7++)
                    if (r7 != (int)rk) st_clu(peer_p[r7] + poff, pd);
            }
        }

        // ---- split barrier: publish DSMEM stores now, overlap the rest ----
        CLUSTER_ARRIVE();

        if (w < 3) {
            ys[((size_t)t * B_ + bg0 + eb) * H_ + egu] = nh;
            if (t == T_ - 1) hs_out[(size_t)(bg0 + eb) * H_ + egu] = nh;
            if (t + 1 < T_) {                 // gi prefetch for t+1 flies during the wait
                const float* gp = gi + ((size_t)(t + 1) * B_ + bg0 + eb) * G3 + egu;
                gir = gp[0]; giz = gp[256]; gin = gp[512];
            }
        }

        CLUSTER_WAIT();
    }

    // layer-0 final carry (skip, d) for layer 1
    if (layer == 0 && w == 3 && lane < GB && rk == 0) {
        float ps = 0.f;
#pragma unroll
        for (int r = 0; r < CSZ; r++) ps += parts_s[r][lane];
        advance_state(su, sd, ss, sigm_fast(ps + lb_));
        g_dcar[bg0 + lane] = sd; g_skipc[bg0 + lane] = ss;
    }
}

// ---------------- launcher ----------------
extern "C" void kernel_launch(void* const* d_in, const int* in_sizes, int n_in,
                              void* d_out, int out_size) {
    const float* x   = (const float*)d_in[0];
    const float* hid = (const float*)d_in[1];
    const float* wih = (const float*)d_in[2];
    const float* whh = (const float*)d_in[3];
    const float* bih = (const float*)d_in[4];
    const float* bhh = (const float*)d_in[5];
    const float* lw  = (const float*)d_in[6];
    const float* lb  = (const float*)d_in[7];
    float* out = (float*)d_out;

    dim3 ggrid(T_ * B_ / 128, G3 / 128);   // (144, 6)
    gemm_xw<<<ggrid, 256>>>(x, 0, wih);
    rec_kernel<<<NCTA, THR>>>(0, hid, whh, bih, bhh, lw, lb, out);
    gemm_xw<<<ggrid, 256>>>(x, 1, wih);
    rec_kernel<<<NCTA, THR>>>(1, hid, whh, bih, bhh, lw, lb, out);
}